// round 7
// baseline (speedup 1.0000x reference)
#include <cuda_runtime.h>
#include <cuda_bf16.h>

// Problem constants
#define NB     50      // buckets
#define HID    32
#define HALF   16
#define GRID   608     // 152 SMs * 4
#define BLOCK  256

// Precomputed tables (device globals — no allocation allowed)
__device__ float4 g_vs4[NB * 8];   // v[id][32] folded W2@Wh, stored as 8 float4 chunks, XOR-swizzled
__device__ float  g_c[NB];         // b2 . Wh[id] + bh[id]
__device__ float4 g_w1p[HID];      // {W1[0][j], W1[1][j], b1[j], 0}

// ---------------------------------------------------------------------------
// Kernel 1: fold W2 into per-bucket heads.
//   v[id][j] = sum_m W2[j,m] * Wh[id,m]
//   c[id]    = sum_m b2[m]  * Wh[id,m] + bh[id]
// Swizzled float4 layout: chunk q (j=4q..4q+3) of bucket id goes to slot
//   g_vs4[id*8 + (q ^ (id&7))]  -> shared-mem bank-group = q ^ (id&7).
// ---------------------------------------------------------------------------
__global__ void lw_precompute(const float* __restrict__ W1,
                              const float* __restrict__ b1,
                              const float* __restrict__ W2,
                              const float* __restrict__ b2,
                              const float* __restrict__ Wh,
                              const float* __restrict__ bh) {
    int t = blockIdx.x * blockDim.x + threadIdx.x;
    if (t < NB * HID) {
        int id = t >> 5;
        int j  = t & 31;
        float acc = 0.f;
#pragma unroll
        for (int m = 0; m < HALF; m++)
            acc = fmaf(W2[j * HALF + m], Wh[id * HALF + m], acc);
        int q  = j >> 2;
        int tt = j & 3;
        reinterpret_cast<float*>(g_vs4)[(id * 8 + (q ^ (id & 7))) * 4 + tt] = acc;
    } else if (t < NB * HID + NB) {
        int id = t - NB * HID;
        float acc = bh[id];
#pragma unroll
        for (int m = 0; m < HALF; m++)
            acc = fmaf(b2[m], Wh[id * HALF + m], acc);
        g_c[id] = acc;
    } else if (t < NB * HID + NB + HID) {
        int j = t - (NB * HID + NB);
        g_w1p[j] = make_float4(W1[j], W1[HID + j], b1[j], 0.f);
    }
}

// ---------------------------------------------------------------------------
// Kernel 2: main. out[r] = sum_j relu(x0*A_j + x1*B_j + C_j) * v[id][j] + c[id]
// 4 rows per thread, q-outer / row-inner so the W1 broadcast LDS is shared.
// ---------------------------------------------------------------------------
__global__ __launch_bounds__(BLOCK)
void lw_main(const float2* __restrict__ x,
             const int*    __restrict__ buckets,
             float*        __restrict__ out,
             int B) {
    __shared__ float4 s_vs4[NB * 8];
    __shared__ float4 s_w1p[HID];
    __shared__ float  s_c[NB];

    // Stage tables into shared
    for (int i = threadIdx.x; i < NB * 8; i += BLOCK) s_vs4[i] = g_vs4[i];
    if (threadIdx.x < HID) s_w1p[threadIdx.x] = g_w1p[threadIdx.x];
    if (threadIdx.x < NB)  s_c[threadIdx.x]   = g_c[threadIdx.x];
    __syncthreads();

    const int T   = gridDim.x * blockDim.x;
    const int tid = blockIdx.x * blockDim.x + threadIdx.x;

    for (long long base = tid; base < B; base += 4LL * T) {
        int    r[4];
        bool   m[4];
        float2 xv[4];
        int    vb[4], sw[4];
        float  cadd[4];
        float  acc0[4], acc1[4];

#pragma unroll
        for (int k = 0; k < 4; k++) {
            long long rr = base + (long long)k * T;
            m[k] = rr < (long long)B;
            int ri = m[k] ? (int)rr : 0;
            r[k] = ri;
            xv[k] = x[ri];
            int id = buckets[ri];
            id = (id >= NB) ? (NB - 1) : (id < 0 ? 0 : id);
            vb[k]  = id * 8;
            sw[k]  = id & 7;
            cadd[k] = s_c[id];
            acc0[k] = 0.f;
            acc1[k] = 0.f;
        }

#pragma unroll
        for (int q = 0; q < 8; q++) {
            // layer-1 weights for j = 4q..4q+3 (broadcast across warp)
            const float4 w0 = s_w1p[q * 4 + 0];
            const float4 w1 = s_w1p[q * 4 + 1];
            const float4 w2 = s_w1p[q * 4 + 2];
            const float4 w3 = s_w1p[q * 4 + 3];
#pragma unroll
            for (int k = 0; k < 4; k++) {
                const float4 v = s_vs4[vb[k] + (q ^ sw[k])];
                const float xa = xv[k].x, xb = xv[k].y;
                float h0 = fmaxf(fmaf(xa, w0.x, fmaf(xb, w0.y, w0.z)), 0.f);
                float h1 = fmaxf(fmaf(xa, w1.x, fmaf(xb, w1.y, w1.z)), 0.f);
                float h2 = fmaxf(fmaf(xa, w2.x, fmaf(xb, w2.y, w2.z)), 0.f);
                float h3 = fmaxf(fmaf(xa, w3.x, fmaf(xb, w3.y, w3.z)), 0.f);
                acc0[k] = fmaf(h0, v.x, acc0[k]);
                acc1[k] = fmaf(h1, v.y, acc1[k]);
                acc0[k] = fmaf(h2, v.z, acc0[k]);
                acc1[k] = fmaf(h3, v.w, acc1[k]);
            }
        }

#pragma unroll
        for (int k = 0; k < 4; k++)
            if (m[k]) out[r[k]] = acc0[k] + acc1[k] + cadd[k];
    }
}

// ---------------------------------------------------------------------------
// Inputs (metadata order): x[B,2] f32, buckets[B] i32, W1[2,32], b1[32],
//                          W2[32,16], b2[16], Wh[50,16], bh[50]
// Output: float[B]
// ---------------------------------------------------------------------------
extern "C" void kernel_launch(void* const* d_in, const int* in_sizes, int n_in,
                              void* d_out, int out_size) {
    const float* x  = (const float*)d_in[0];
    const int*   bk = (const int*)d_in[1];
    const float* W1 = (const float*)d_in[2];
    const float* b1 = (const float*)d_in[3];
    const float* W2 = (const float*)d_in[4];
    const float* b2 = (const float*)d_in[5];
    const float* Wh = (const float*)d_in[6];
    const float* bh = (const float*)d_in[7];
    float* out = (float*)d_out;

    const int B = in_sizes[1];  // buckets element count == rows

    lw_precompute<<<14, 128>>>(W1, b1, W2, b2, Wh, bh);
    lw_main<<<GRID, BLOCK>>>((const float2*)x, bk, out, B);
}

// round 11
// speedup vs baseline: 1.3023x; 1.3023x over previous
#include <cuda_runtime.h>
#include <cuda_bf16.h>

// Problem constants
#define NB     50      // buckets
#define HID    32
#define HALF   16
#define GRID   304     // 152 SMs * 2 resident blocks (persistent grid-stride)
#define BLOCK  256

// Precomputed tables (device globals — no allocation allowed).
// g_v layout: per bucket id, 9 float4 slots at stride 9:
//   slots 0..7 = v[id][4q..4q+3]  (v = W2 @ Wh[id], folded layer-2)
//   slot  8.x  = c[id] = b2 . Wh[id] + bh[id]   (folded bias)
// Bank-group of slot q is (9*id+q) mod 8 = (id+q) mod 8 -> lanes with
// different (id mod 8) never collide; addressing is linear (imm offsets).
__device__ float4 g_v[NB * 9];
// W1/b1 as SoA float4 chunks: A=W1[0][:], B=W1[1][:], C=b1[:]
__device__ float4 g_A[HID / 4];
__device__ float4 g_B[HID / 4];
__device__ float4 g_C[HID / 4];

// ---------------------------------------------------------------------------
// Kernel 1: fold W2 (and b2,bh) into per-bucket heads + repack W1.
// ---------------------------------------------------------------------------
__global__ void lw_precompute(const float* __restrict__ W1,
                              const float* __restrict__ b1,
                              const float* __restrict__ W2,
                              const float* __restrict__ b2,
                              const float* __restrict__ Wh,
                              const float* __restrict__ bh) {
    int t = blockIdx.x * blockDim.x + threadIdx.x;
    if (t < NB * HID) {
        int id = t >> 5;
        int j  = t & 31;
        float acc = 0.f;
#pragma unroll
        for (int m = 0; m < HALF; m++)
            acc = fmaf(W2[j * HALF + m], Wh[id * HALF + m], acc);
        reinterpret_cast<float*>(g_v)[id * 36 + j] = acc;  // slot j/4, lane j&3
    } else if (t < NB * HID + NB) {
        int id = t - NB * HID;
        float acc = bh[id];
#pragma unroll
        for (int m = 0; m < HALF; m++)
            acc = fmaf(b2[m], Wh[id * HALF + m], acc);
        reinterpret_cast<float*>(g_v)[id * 36 + 32] = acc;  // slot 8 .x
    } else if (t < NB * HID + NB + HID) {
        int j = t - (NB * HID + NB);
        reinterpret_cast<float*>(g_A)[j] = W1[j];
        reinterpret_cast<float*>(g_B)[j] = W1[HID + j];
        reinterpret_cast<float*>(g_C)[j] = b1[j];
    }
}

// ---------------------------------------------------------------------------
// Kernel 2: main. Two consecutive rows per thread (float4 x, int2 buckets,
// float2 out). out[r] = sum_j relu(x0*A_j + x1*B_j + C_j) * v[id][j] + c[id]
// ---------------------------------------------------------------------------
__global__ __launch_bounds__(BLOCK, 2)
void lw_main(const float4* __restrict__ x2,
             const int2*   __restrict__ bk2,
             float2*       __restrict__ out2,
             int npairs,
             const float*  __restrict__ x_s,
             const int*    __restrict__ bk_s,
             float*        __restrict__ out_s,
             int B) {
    __shared__ float4 s_v[NB * 9];
    __shared__ float4 s_A[HID / 4];
    __shared__ float4 s_B[HID / 4];
    __shared__ float4 s_C[HID / 4];

    for (int i = threadIdx.x; i < NB * 9; i += BLOCK) s_v[i] = g_v[i];
    if (threadIdx.x < HID / 4) {
        s_A[threadIdx.x] = g_A[threadIdx.x];
        s_B[threadIdx.x] = g_B[threadIdx.x];
        s_C[threadIdx.x] = g_C[threadIdx.x];
    }
    __syncthreads();

    const int T = gridDim.x * blockDim.x;
    const int tid = blockIdx.x * blockDim.x + threadIdx.x;

    for (int p = tid; p < npairs; p += T) {
        const int2   ids = bk2[p];
        const float4 xp  = x2[p];
        const unsigned i0 = min((unsigned)ids.x, NB - 1u);
        const unsigned i1 = min((unsigned)ids.y, NB - 1u);
        const float4* v0 = s_v + i0 * 9;
        const float4* v1 = s_v + i1 * 9;

        float a0 = v0[8].x, b0 = 0.f;   // c folded into acc init
        float a1 = v1[8].x, b1r = 0.f;

#pragma unroll
        for (int q = 0; q < 8; q++) {
            const float4 A  = s_A[q];
            const float4 Bw = s_B[q];
            const float4 C  = s_C[q];
            const float4 u0 = v0[q];
            const float4 u1 = v1[q];
            float h;
            // row 0 (x = xp.x, xp.y)
            h = fmaxf(fmaf(xp.x, A.x, fmaf(xp.y, Bw.x, C.x)), 0.f); a0 = fmaf(h, u0.x, a0);
            h = fmaxf(fmaf(xp.x, A.y, fmaf(xp.y, Bw.y, C.y)), 0.f); b0 = fmaf(h, u0.y, b0);
            h = fmaxf(fmaf(xp.x, A.z, fmaf(xp.y, Bw.z, C.z)), 0.f); a0 = fmaf(h, u0.z, a0);
            h = fmaxf(fmaf(xp.x, A.w, fmaf(xp.y, Bw.w, C.w)), 0.f); b0 = fmaf(h, u0.w, b0);
            // row 1 (x = xp.z, xp.w)
            h = fmaxf(fmaf(xp.z, A.x, fmaf(xp.w, Bw.x, C.x)), 0.f); a1  = fmaf(h, u1.x, a1);
            h = fmaxf(fmaf(xp.z, A.y, fmaf(xp.w, Bw.y, C.y)), 0.f); b1r = fmaf(h, u1.y, b1r);
            h = fmaxf(fmaf(xp.z, A.z, fmaf(xp.w, Bw.z, C.z)), 0.f); a1  = fmaf(h, u1.z, a1);
            h = fmaxf(fmaf(xp.z, A.w, fmaf(xp.w, Bw.w, C.w)), 0.f); b1r = fmaf(h, u1.w, b1r);
        }
        out2[p] = make_float2(a0 + b0, a1 + b1r);
    }

    // Odd-B tail: one scalar row handled by a single thread.
    if ((B & 1) && tid == 0) {
        const int r = B - 1;
        const unsigned id = min((unsigned)bk_s[r], NB - 1u);
        const float4* v = s_v + id * 9;
        const float xa = x_s[2 * r], xb = x_s[2 * r + 1];
        float acc = v[8].x;
#pragma unroll
        for (int q = 0; q < 8; q++) {
            const float4 A  = s_A[q];
            const float4 Bw = s_B[q];
            const float4 C  = s_C[q];
            const float4 u  = v[q];
            float h;
            h = fmaxf(fmaf(xa, A.x, fmaf(xb, Bw.x, C.x)), 0.f); acc = fmaf(h, u.x, acc);
            h = fmaxf(fmaf(xa, A.y, fmaf(xb, Bw.y, C.y)), 0.f); acc = fmaf(h, u.y, acc);
            h = fmaxf(fmaf(xa, A.z, fmaf(xb, Bw.z, C.z)), 0.f); acc = fmaf(h, u.z, acc);
            h = fmaxf(fmaf(xa, A.w, fmaf(xb, Bw.w, C.w)), 0.f); acc = fmaf(h, u.w, acc);
        }
        out_s[r] = acc;
    }
}

// ---------------------------------------------------------------------------
// Inputs (metadata order): x[B,2] f32, buckets[B] i32, W1[2,32], b1[32],
//                          W2[32,16], b2[16], Wh[50,16], bh[50]
// Output: float[B]
// ---------------------------------------------------------------------------
extern "C" void kernel_launch(void* const* d_in, const int* in_sizes, int n_in,
                              void* d_out, int out_size) {
    const float* x  = (const float*)d_in[0];
    const int*   bk = (const int*)d_in[1];
    const float* W1 = (const float*)d_in[2];
    const float* b1 = (const float*)d_in[3];
    const float* W2 = (const float*)d_in[4];
    const float* b2 = (const float*)d_in[5];
    const float* Wh = (const float*)d_in[6];
    const float* bh = (const float*)d_in[7];
    float* out = (float*)d_out;

    const int B = in_sizes[1];
    const int npairs = B >> 1;

    lw_precompute<<<14, 128>>>(W1, b1, W2, b2, Wh, bh);
    lw_main<<<GRID, BLOCK>>>((const float4*)x, (const int2*)bk, (float2*)out,
                             npairs, x, bk, out, B);
}